// round 11
// baseline (speedup 1.0000x reference)
#include <cuda_runtime.h>

#define VV 100000
#define DD 128
#define MM 200
#define HOPS 3
#define NKS 74                 // k-split blocks; 74*2 = 148 = one wave
#define KSTEPS 3125            // 100000 / 32
#define MPAD 256

#define SAF 8192               // A-stage floats (256*32)
#define SBF 2048               // B-stage floats (64*32)
#define STAGEF (SAF + 2*SBF)   // 12288 floats = 48KB per stage
#define NSTG 3
#define GSMEM (NSTG * STAGEF * 4)   // 144KB dynamic
#define HSMEM (MM * DD * 4)         // 102.4KB dynamic for k_hops

// ---------------- scratch (allocation-free) ----------------
__device__ float g_qd[DD];
__device__ float g_A2[MPAD * DD];   // tA + memory @ Wa^T (split-K atomic accum)
__device__ float g_C2[MPAD * DD];   // tC + memory @ Wc^T

__device__ __forceinline__ float warp_sum(float v) {
#pragma unroll
    for (int o = 16; o > 0; o >>= 1) v += __shfl_xor_sync(0xffffffffu, v, o);
    return v;
}

__device__ __forceinline__ unsigned f2tf32(float x) {
    unsigned r;
    asm("cvt.rna.tf32.f32 %0, %1;" : "=r"(r) : "f"(x));
    return r;
}

__device__ __forceinline__ void mma8(float* c, const unsigned* a, unsigned b0, unsigned b1) {
    asm volatile(
        "mma.sync.aligned.m16n8k8.row.col.f32.tf32.tf32.f32 "
        "{%0,%1,%2,%3},{%4,%5,%6,%7},{%8,%9},{%0,%1,%2,%3};"
        : "+f"(c[0]), "+f"(c[1]), "+f"(c[2]), "+f"(c[3])
        : "r"(a[0]), "r"(a[1]), "r"(a[2]), "r"(a[3]), "r"(b0), "r"(b1));
}

__device__ __forceinline__ void cpa16(unsigned saddr, const void* g) {
    asm volatile("cp.async.ca.shared.global [%0], [%1], 16;\n"
                 :: "r"(saddr), "l"(g));
}

// swizzled smem index for element (r, k) in a 32-wide tile (16B-granular XOR)
__device__ __forceinline__ int swz(int r, int k) {
    return r * 32 + (k ^ ((r & 7) << 2));
}

// fold temporal matrices into the accumulators (reset every replay)
__global__ void k_init(const float* __restrict__ tA, const float* __restrict__ tC) {
    int i = blockIdx.x * blockDim.x + threadIdx.x;
    if (i < MPAD * DD) {
        g_A2[i] = (i < MM * DD) ? tA[i] : 0.f;
        g_C2[i] = (i < MM * DD) ? tC[i] : 0.f;
    }
    if (i < DD) g_qd[i] = 0.f;
}

// ---------------- qd0 = question @ Wb^T (fp32 exact) ----------------
__global__ void __launch_bounds__(256) k_quesd(
    const float* __restrict__ Wb, const float* __restrict__ question) {
    __shared__ float sred[8];
    const int tid = threadIdx.x, lane = tid & 31, w = tid >> 5;
    const int r = blockIdx.x >> 1, half = blockIdx.x & 1;
    const float4* wr = (const float4*)(Wb + (size_t)r * VV + half * 50000);
    const float4* qv = (const float4*)(question + half * 50000);
    float acc = 0.f;
    for (int q = tid; q < 12500; q += 256) {
        float4 a = wr[q], b = qv[q];
        acc += a.x * b.x + a.y * b.y + a.z * b.z + a.w * b.w;
    }
    acc = warp_sum(acc);
    if (lane == 0) sred[w] = acc;
    __syncthreads();
    if (w == 0) {
        float x = (lane < 8) ? sred[lane] : 0.f;
        x = warp_sum(x);
        if (lane == 0) atomicAdd(&g_qd[r], x);
    }
}

// ---------------- A2/C2 GEMM: 1xTF32, cp.async 3-stage ring, 1 sync/step ------
// grid (NKS, 2 n-halves). Block 512. Tile M=256, N=64, K=32. Both matrices/block.
__global__ void __launch_bounds__(512, 1) k_gemm(
    const float* __restrict__ mem, const float* __restrict__ Wa,
    const float* __restrict__ Wc) {
    extern __shared__ float dsm[];

    const int tid = threadIdx.x, lane = tid & 31, w = tid >> 5;
    const int gid = lane >> 2, tig = lane & 3;
    const int nh = blockIdx.y;
    const int wm = w & 7, wn = w >> 3;
    const int mb = wm * 32, nb = wn * 32;
    const int s0 = (int)blockIdx.x * KSTEPS / NKS;
    const int s1 = ((int)blockIdx.x + 1) * KSTEPS / NKS;

    int amc[4];
#pragma unroll
    for (int i = 0; i < 4; i++) {
        int m = (tid + i * 512) >> 3;
        amc[i] = (m < MM) ? m : (MM - 1);   // clamp: rows>=200 garbage, never read
    }
    const int ac4 = (tid & 7) * 4;
    const int bn = tid >> 3;

    const unsigned sbase = (unsigned)__cvta_generic_to_shared(dsm);

    float accA[2][4][4], accC[2][4][4];
#pragma unroll
    for (int mt = 0; mt < 2; mt++)
#pragma unroll
        for (int nt = 0; nt < 4; nt++)
#pragma unroll
            for (int j = 0; j < 4; j++) { accA[mt][nt][j] = 0.f; accC[mt][nt][j] = 0.f; }

    auto issue = [&](int s, int p) {
        const int k0 = s * 32;
        const unsigned st = sbase + (unsigned)(p * STAGEF) * 4u;
#pragma unroll
        for (int i = 0; i < 4; i++)
            cpa16(st + (unsigned)swz(amc[i], ac4) * 4u,
                  mem + (size_t)amc[i] * VV + k0 + ac4);
        cpa16(st + (unsigned)(SAF + swz(bn, ac4)) * 4u,
              Wa + (size_t)(nh * 64 + bn) * VV + k0 + ac4);
        cpa16(st + (unsigned)(SAF + SBF + swz(bn, ac4)) * 4u,
              Wc + (size_t)(nh * 64 + bn) * VV + k0 + ac4);
    };

    // prologue: 2 stages in flight
    issue(s0, 0);
    asm volatile("cp.async.commit_group;\n");
    issue(s0 + 1, 1);
    asm volatile("cp.async.commit_group;\n");

    for (int s = s0; s < s1; s++) {
        const int p = (s - s0) % NSTG;
        asm volatile("cp.async.wait_group 1;\n");   // stage p landed
        __syncthreads();                            // visible to all; slot (s-1) free

        // refill slot of step s-1 NOW (freedom proven by the barrier above);
        // these LDGs get this whole compute loop plus the next one to land
        if (s + 2 < s1) issue(s + 2, (s + 2 - s0) % NSTG);
        asm volatile("cp.async.commit_group;\n");

        const float* fA  = dsm + p * STAGEF;
        const float* fBa = fA + SAF;
        const float* fBc = fBa + SBF;
#pragma unroll
        for (int q = 0; q < 4; q++) {
            const int c0 = q * 8 + tig;
            unsigned a[2][4];
#pragma unroll
            for (int mt = 0; mt < 2; mt++) {
                const int r = mb + mt * 16 + gid;
                a[mt][0] = f2tf32(fA[swz(r, c0)]);
                a[mt][1] = f2tf32(fA[swz(r + 8, c0)]);
                a[mt][2] = f2tf32(fA[swz(r, c0 + 4)]);
                a[mt][3] = f2tf32(fA[swz(r + 8, c0 + 4)]);
            }
#pragma unroll
            for (int nt = 0; nt < 4; nt++) {
                const int n = nb + nt * 8 + gid;
                unsigned ba0 = f2tf32(fBa[swz(n, c0)]), ba1 = f2tf32(fBa[swz(n, c0 + 4)]);
                unsigned bc0 = f2tf32(fBc[swz(n, c0)]), bc1 = f2tf32(fBc[swz(n, c0 + 4)]);
#pragma unroll
                for (int mt = 0; mt < 2; mt++) {
                    mma8(accA[mt][nt], a[mt], ba0, ba1);
                    mma8(accC[mt][nt], a[mt], bc0, bc1);
                }
            }
        }
    }

    // split-K accumulate (on top of tA/tC baseline from k_init)
#pragma unroll
    for (int mt = 0; mt < 2; mt++)
#pragma unroll
        for (int nt = 0; nt < 4; nt++) {
            const int r0 = mb + mt * 16 + gid;
            const int c0 = nh * 64 + nb + nt * 8 + tig * 2;
            atomicAdd(&g_A2[r0 * DD + c0],           accA[mt][nt][0]);
            atomicAdd(&g_A2[r0 * DD + c0 + 1],       accA[mt][nt][1]);
            atomicAdd(&g_A2[(r0 + 8) * DD + c0],     accA[mt][nt][2]);
            atomicAdd(&g_A2[(r0 + 8) * DD + c0 + 1], accA[mt][nt][3]);
            atomicAdd(&g_C2[r0 * DD + c0],           accC[mt][nt][0]);
            atomicAdd(&g_C2[r0 * DD + c0 + 1],       accC[mt][nt][1]);
            atomicAdd(&g_C2[(r0 + 8) * DD + c0],     accC[mt][nt][2]);
            atomicAdd(&g_C2[(r0 + 8) * DD + c0 + 1], accC[mt][nt][3]);
        }
}

// ------- 3 hops, single block: At in registers, C2 cached in shared memory ------
__global__ void __launch_bounds__(512) k_hops() {
    extern __shared__ float sC[];             // [MM * DD] = 102.4 KB
    __shared__ float sqd[DD];
    __shared__ float sP[256];
    __shared__ float sred[512];
    const int tid = threadIdx.x, lane = tid & 31, w = tid >> 5;
    const int mbase = w * 13;                 // warp-owned A rows (13 each)

    // C2 -> smem (one bulk copy), At -> registers
    {
        const float4* src = (const float4*)g_C2;
        float4* dst = (float4*)sC;
        for (int i = tid; i < MM * DD / 4; i += 512) dst[i] = src[i];
    }
    float ra[13][4];
#pragma unroll
    for (int i = 0; i < 13; i++) {
        const int m = mbase + i;
#pragma unroll
        for (int k = 0; k < 4; k++)
            ra[i][k] = (m < MM) ? g_A2[m * DD + lane + 32 * k] : 0.f;
    }
    if (tid < DD) sqd[tid] = g_qd[tid];
    __syncthreads();

    for (int h = 0; h < HOPS; h++) {
        float q0 = sqd[lane], q1 = sqd[lane + 32], q2 = sqd[lane + 64], q3 = sqd[lane + 96];
#pragma unroll
        for (int i = 0; i < 13; i++) {
            const int m = mbase + i;
            float acc = ra[i][0] * q0 + ra[i][1] * q1 + ra[i][2] * q2 + ra[i][3] * q3;
            acc = warp_sum(acc);
            if (lane == 0 && m < MM) sP[m] = acc;
        }
        __syncthreads();
        sred[tid] = (tid < MM) ? sP[tid] : -3.4e38f;
        __syncthreads();
        for (int s = 256; s >= 1; s >>= 1) {
            if (tid < s) sred[tid] = fmaxf(sred[tid], sred[tid + s]);
            __syncthreads();
        }
        float mx = sred[0];
        __syncthreads();
        float e = (tid < MM) ? __expf(sP[tid] - mx) : 0.f;
        sred[tid] = e;
        __syncthreads();
        for (int s = 256; s >= 1; s >>= 1) {
            if (tid < s) sred[tid] += sred[tid + s];
            __syncthreads();
        }
        float inv = 1.f / sred[0];
        __syncthreads();
        if (tid < MM) sP[tid] = e * inv;
        __syncthreads();
        // o[d] = qd[d] + sum_m P[m]*C2[m][d]  (4-way m-split, all smem)
        {
            const int q = tid >> 7, d = tid & 127;
            float part = 0.f;
#pragma unroll 10
            for (int m = q * 50; m < q * 50 + 50; m++)
                part += sP[m] * sC[m * DD + d];
            sred[tid] = part;
            __syncthreads();
            float o = 0.f;
            if (q == 0)
                o = sqd[d] + sred[d] + sred[d + 128] + sred[d + 256] + sred[d + 384];
            __syncthreads();
            if (q == 0) sqd[d] = o;
            __syncthreads();
        }
    }
    if (tid < DD) g_qd[tid] = sqd[tid];
}

// ---------------- out[v] = o . Wout[v] ----------------
__global__ void __launch_bounds__(256) k_out(
    const float* __restrict__ Wout, float* __restrict__ out) {
    const int lane = threadIdx.x & 31;
    const int gw = (blockIdx.x * 256 + threadIdx.x) >> 5;
    const int nw = (gridDim.x * 256) >> 5;
    float4 qv = *(const float4*)(&g_qd[lane * 4]);
    for (int r = gw; r < VV; r += nw) {
        float4 wv = ((const float4*)(Wout + (size_t)r * DD))[lane];
        float acc = qv.x * wv.x + qv.y * wv.y + qv.z * wv.z + qv.w * wv.w;
        acc = warp_sum(acc);
        if (lane == 0) out[r] = acc;
    }
}

extern "C" void kernel_launch(void* const* d_in, const int* in_sizes, int n_in,
                              void* d_out, int out_size) {
    const float* question = (const float*)d_in[0];
    const float* memory   = (const float*)d_in[1];
    const float* Wa       = (const float*)d_in[2];
    const float* Wb       = (const float*)d_in[3];
    const float* Wc       = (const float*)d_in[4];
    const float* Wout     = (const float*)d_in[5];
    const float* tA       = (const float*)d_in[6];
    const float* tC       = (const float*)d_in[7];
    float* out = (float*)d_out;

    // idempotent dynamic-smem opt-ins (no static guards)
    cudaFuncSetAttribute(k_gemm, cudaFuncAttributeMaxDynamicSharedMemorySize, GSMEM);
    cudaFuncSetAttribute(k_hops, cudaFuncAttributeMaxDynamicSharedMemorySize, HSMEM);

    k_init<<<32, 1024>>>(tA, tC);
    k_gemm<<<dim3(NKS, 2), 512, GSMEM>>>(memory, Wa, Wc);
    k_quesd<<<DD * 2, 256>>>(Wb, question);
    k_hops<<<1, 512, HSMEM>>>();
    k_out<<<592, 256>>>(Wout, out);
}

// round 13
// speedup vs baseline: 1.0002x; 1.0002x over previous
#include <cuda_runtime.h>

#define VV 100000
#define DD 128
#define MM 200
#define HOPS 3
#define NKS 74                 // k-split blocks; 74*2 = 148 = one wave
#define KSTEPS 3125            // 100000 / 32
#define MPAD 256

#define SAF 8192               // A-stage floats (256*32)
#define SBF 2048               // B-stage floats (64*32)
#define STAGEF (SAF + 2*SBF)   // 12288 floats = 48KB per stage
#define NSTG 3
#define GSMEM (NSTG * STAGEF * 4)   // 144KB dynamic
#define HSMEM (MM * DD * 4)         // 102.4KB dynamic for k_hops

// ---------------- scratch (allocation-free) ----------------
__device__ float g_qd[DD];
__device__ float g_A2[MPAD * DD];   // tA + memory @ Wa^T (split-K atomic accum)
__device__ float g_C2[MPAD * DD];   // tC + memory @ Wc^T

__device__ __forceinline__ float warp_sum(float v) {
#pragma unroll
    for (int o = 16; o > 0; o >>= 1) v += __shfl_xor_sync(0xffffffffu, v, o);
    return v;
}

__device__ __forceinline__ unsigned f2tf32(float x) {
    unsigned r;
    asm("cvt.rna.tf32.f32 %0, %1;" : "=r"(r) : "f"(x));
    return r;
}

__device__ __forceinline__ void mma8(float* c, const unsigned* a, unsigned b0, unsigned b1) {
    asm volatile(
        "mma.sync.aligned.m16n8k8.row.col.f32.tf32.tf32.f32 "
        "{%0,%1,%2,%3},{%4,%5,%6,%7},{%8,%9},{%0,%1,%2,%3};"
        : "+f"(c[0]), "+f"(c[1]), "+f"(c[2]), "+f"(c[3])
        : "r"(a[0]), "r"(a[1]), "r"(a[2]), "r"(a[3]), "r"(b0), "r"(b1));
}

__device__ __forceinline__ void cpa16(unsigned saddr, const void* g) {
    asm volatile("cp.async.ca.shared.global [%0], [%1], 16;\n"
                 :: "r"(saddr), "l"(g));
}

// swizzled smem index for element (r, k) in a 32-wide tile (16B-granular XOR)
__device__ __forceinline__ int swz(int r, int k) {
    return r * 32 + (k ^ ((r & 7) << 2));
}

// fold temporal matrices into the accumulators (reset every replay)
__global__ void k_init(const float* __restrict__ tA, const float* __restrict__ tC) {
    int i = blockIdx.x * blockDim.x + threadIdx.x;
    if (i < MPAD * DD) {
        g_A2[i] = (i < MM * DD) ? tA[i] : 0.f;
        g_C2[i] = (i < MM * DD) ? tC[i] : 0.f;
    }
    if (i < DD) g_qd[i] = 0.f;
}

// ---------------- qd0 = question @ Wb^T (fp32 exact) ----------------
__global__ void __launch_bounds__(256) k_quesd(
    const float* __restrict__ Wb, const float* __restrict__ question) {
    __shared__ float sred[8];
    const int tid = threadIdx.x, lane = tid & 31, w = tid >> 5;
    const int r = blockIdx.x >> 1, half = blockIdx.x & 1;
    const float4* wr = (const float4*)(Wb + (size_t)r * VV + half * 50000);
    const float4* qv = (const float4*)(question + half * 50000);
    float acc = 0.f;
    for (int q = tid; q < 12500; q += 256) {
        float4 a = wr[q], b = qv[q];
        acc += a.x * b.x + a.y * b.y + a.z * b.z + a.w * b.w;
    }
    acc = warp_sum(acc);
    if (lane == 0) sred[w] = acc;
    __syncthreads();
    if (w == 0) {
        float x = (lane < 8) ? sred[lane] : 0.f;
        x = warp_sum(x);
        if (lane == 0) atomicAdd(&g_qd[r], x);
    }
}

// ---------------- A2/C2 GEMM: 1xTF32, cp.async 3-stage ring, 1 sync/step ------
// grid (NKS, 2 n-halves). Block 512. Tile M=256, N=64, K=32. Both matrices/block.
__global__ void __launch_bounds__(512, 1) k_gemm(
    const float* __restrict__ mem, const float* __restrict__ Wa,
    const float* __restrict__ Wc) {
    extern __shared__ float dsm[];

    const int tid = threadIdx.x, lane = tid & 31, w = tid >> 5;
    const int gid = lane >> 2, tig = lane & 3;
    const int nh = blockIdx.y;
    const int wm = w & 7, wn = w >> 3;
    const int mb = wm * 32, nb = wn * 32;
    const int s0 = (int)blockIdx.x * KSTEPS / NKS;
    const int s1 = ((int)blockIdx.x + 1) * KSTEPS / NKS;

    int amc[4];
#pragma unroll
    for (int i = 0; i < 4; i++) {
        int m = (tid + i * 512) >> 3;
        amc[i] = (m < MM) ? m : (MM - 1);   // clamp: rows>=200 garbage, never read
    }
    const int ac4 = (tid & 7) * 4;
    const int bn = tid >> 3;

    const unsigned sbase = (unsigned)__cvta_generic_to_shared(dsm);

    float accA[2][4][4], accC[2][4][4];
#pragma unroll
    for (int mt = 0; mt < 2; mt++)
#pragma unroll
        for (int nt = 0; nt < 4; nt++)
#pragma unroll
            for (int j = 0; j < 4; j++) { accA[mt][nt][j] = 0.f; accC[mt][nt][j] = 0.f; }

    auto issue = [&](int s, int p) {
        const int k0 = s * 32;
        const unsigned st = sbase + (unsigned)(p * STAGEF) * 4u;
#pragma unroll
        for (int i = 0; i < 4; i++)
            cpa16(st + (unsigned)swz(amc[i], ac4) * 4u,
                  mem + (size_t)amc[i] * VV + k0 + ac4);
        cpa16(st + (unsigned)(SAF + swz(bn, ac4)) * 4u,
              Wa + (size_t)(nh * 64 + bn) * VV + k0 + ac4);
        cpa16(st + (unsigned)(SAF + SBF + swz(bn, ac4)) * 4u,
              Wc + (size_t)(nh * 64 + bn) * VV + k0 + ac4);
    };

    // prologue: 2 stages in flight
    issue(s0, 0);
    asm volatile("cp.async.commit_group;\n");
    issue(s0 + 1, 1);
    asm volatile("cp.async.commit_group;\n");

    for (int s = s0; s < s1; s++) {
        const int p = (s - s0) % NSTG;
        asm volatile("cp.async.wait_group 1;\n");   // stage p landed
        __syncthreads();                            // visible to all; slot (s-1) free

        // refill slot of step s-1 NOW (freedom proven by the barrier above);
        // these LDGs get this whole compute loop plus the next one to land
        if (s + 2 < s1) issue(s + 2, (s + 2 - s0) % NSTG);
        asm volatile("cp.async.commit_group;\n");

        const float* fA  = dsm + p * STAGEF;
        const float* fBa = fA + SAF;
        const float* fBc = fBa + SBF;
#pragma unroll
        for (int q = 0; q < 4; q++) {
            const int c0 = q * 8 + tig;
            unsigned a[2][4];
#pragma unroll
            for (int mt = 0; mt < 2; mt++) {
                const int r = mb + mt * 16 + gid;
                a[mt][0] = f2tf32(fA[swz(r, c0)]);
                a[mt][1] = f2tf32(fA[swz(r + 8, c0)]);
                a[mt][2] = f2tf32(fA[swz(r, c0 + 4)]);
                a[mt][3] = f2tf32(fA[swz(r + 8, c0 + 4)]);
            }
#pragma unroll
            for (int nt = 0; nt < 4; nt++) {
                const int n = nb + nt * 8 + gid;
                unsigned ba0 = f2tf32(fBa[swz(n, c0)]), ba1 = f2tf32(fBa[swz(n, c0 + 4)]);
                unsigned bc0 = f2tf32(fBc[swz(n, c0)]), bc1 = f2tf32(fBc[swz(n, c0 + 4)]);
#pragma unroll
                for (int mt = 0; mt < 2; mt++) {
                    mma8(accA[mt][nt], a[mt], ba0, ba1);
                    mma8(accC[mt][nt], a[mt], bc0, bc1);
                }
            }
        }
    }

    // split-K accumulate (on top of tA/tC baseline from k_init)
#pragma unroll
    for (int mt = 0; mt < 2; mt++)
#pragma unroll
        for (int nt = 0; nt < 4; nt++) {
            const int r0 = mb + mt * 16 + gid;
            const int c0 = nh * 64 + nb + nt * 8 + tig * 2;
            atomicAdd(&g_A2[r0 * DD + c0],           accA[mt][nt][0]);
            atomicAdd(&g_A2[r0 * DD + c0 + 1],       accA[mt][nt][1]);
            atomicAdd(&g_A2[(r0 + 8) * DD + c0],     accA[mt][nt][2]);
            atomicAdd(&g_A2[(r0 + 8) * DD + c0 + 1], accA[mt][nt][3]);
            atomicAdd(&g_C2[r0 * DD + c0],           accC[mt][nt][0]);
            atomicAdd(&g_C2[r0 * DD + c0 + 1],       accC[mt][nt][1]);
            atomicAdd(&g_C2[(r0 + 8) * DD + c0],     accC[mt][nt][2]);
            atomicAdd(&g_C2[(r0 + 8) * DD + c0 + 1], accC[mt][nt][3]);
        }
}

// ------- 3 hops, single block: At in registers, C2 cached in shared memory ------
__global__ void __launch_bounds__(512) k_hops() {
    extern __shared__ float sC[];             // [MM * DD] = 102.4 KB
    __shared__ float sqd[DD];
    __shared__ float sP[256];
    __shared__ float sred[512];
    const int tid = threadIdx.x, lane = tid & 31, w = tid >> 5;
    const int mbase = w * 13;                 // warp-owned A rows (13 each)

    // C2 -> smem (one bulk copy), At -> registers
    {
        const float4* src = (const float4*)g_C2;
        float4* dst = (float4*)sC;
        for (int i = tid; i < MM * DD / 4; i += 512) dst[i] = src[i];
    }
    float ra[13][4];
#pragma unroll
    for (int i = 0; i < 13; i++) {
        const int m = mbase + i;
#pragma unroll
        for (int k = 0; k < 4; k++)
            ra[i][k] = (m < MM) ? g_A2[m * DD + lane + 32 * k] : 0.f;
    }
    if (tid < DD) sqd[tid] = g_qd[tid];
    __syncthreads();

    for (int h = 0; h < HOPS; h++) {
        float q0 = sqd[lane], q1 = sqd[lane + 32], q2 = sqd[lane + 64], q3 = sqd[lane + 96];
#pragma unroll
        for (int i = 0; i < 13; i++) {
            const int m = mbase + i;
            float acc = ra[i][0] * q0 + ra[i][1] * q1 + ra[i][2] * q2 + ra[i][3] * q3;
            acc = warp_sum(acc);
            if (lane == 0 && m < MM) sP[m] = acc;
        }
        __syncthreads();
        sred[tid] = (tid < MM) ? sP[tid] : -3.4e38f;
        __syncthreads();
        for (int s = 256; s >= 1; s >>= 1) {
            if (tid < s) sred[tid] = fmaxf(sred[tid], sred[tid + s]);
            __syncthreads();
        }
        float mx = sred[0];
        __syncthreads();
        float e = (tid < MM) ? __expf(sP[tid] - mx) : 0.f;
        sred[tid] = e;
        __syncthreads();
        for (int s = 256; s >= 1; s >>= 1) {
            if (tid < s) sred[tid] += sred[tid + s];
            __syncthreads();
        }
        float inv = 1.f / sred[0];
        __syncthreads();
        if (tid < MM) sP[tid] = e * inv;
        __syncthreads();
        // o[d] = qd[d] + sum_m P[m]*C2[m][d]  (4-way m-split, all smem)
        {
            const int q = tid >> 7, d = tid & 127;
            float part = 0.f;
#pragma unroll 10
            for (int m = q * 50; m < q * 50 + 50; m++)
                part += sP[m] * sC[m * DD + d];
            sred[tid] = part;
            __syncthreads();
            float o = 0.f;
            if (q == 0)
                o = sqd[d] + sred[d] + sred[d + 128] + sred[d + 256] + sred[d + 384];
            __syncthreads();
            if (q == 0) sqd[d] = o;
            __syncthreads();
        }
    }
    if (tid < DD) g_qd[tid] = sqd[tid];
}

// ---------------- out[v] = o . Wout[v] ----------------
__global__ void __launch_bounds__(256) k_out(
    const float* __restrict__ Wout, float* __restrict__ out) {
    const int lane = threadIdx.x & 31;
    const int gw = (blockIdx.x * 256 + threadIdx.x) >> 5;
    const int nw = (gridDim.x * 256) >> 5;
    float4 qv = *(const float4*)(&g_qd[lane * 4]);
    for (int r = gw; r < VV; r += nw) {
        float4 wv = ((const float4*)(Wout + (size_t)r * DD))[lane];
        float acc = qv.x * wv.x + qv.y * wv.y + qv.z * wv.z + qv.w * wv.w;
        acc = warp_sum(acc);
        if (lane == 0) out[r] = acc;
    }
}

extern "C" void kernel_launch(void* const* d_in, const int* in_sizes, int n_in,
                              void* d_out, int out_size) {
    const float* question = (const float*)d_in[0];
    const float* memory   = (const float*)d_in[1];
    const float* Wa       = (const float*)d_in[2];
    const float* Wb       = (const float*)d_in[3];
    const float* Wc       = (const float*)d_in[4];
    const float* Wout     = (const float*)d_in[5];
    const float* tA       = (const float*)d_in[6];
    const float* tC       = (const float*)d_in[7];
    float* out = (float*)d_out;

    // idempotent dynamic-smem opt-ins (no static guards)
    cudaFuncSetAttribute(k_gemm, cudaFuncAttributeMaxDynamicSharedMemorySize, GSMEM);
    cudaFuncSetAttribute(k_hops, cudaFuncAttributeMaxDynamicSharedMemorySize, HSMEM);

    k_init<<<32, 1024>>>(tA, tC);
    k_gemm<<<dim3(NKS, 2), 512, GSMEM>>>(memory, Wa, Wc);
    k_quesd<<<DD * 2, 256>>>(Wb, question);
    k_hops<<<1, 512, HSMEM>>>();
    k_out<<<592, 256>>>(Wout, out);
}

// round 15
// speedup vs baseline: 1.0892x; 1.0890x over previous
#include <cuda_runtime.h>

#define VV 100000
#define DD 128
#define MM 200
#define HOPS 3
#define NKS 74                 // k-split blocks; 74*2 = 148 = one wave
#define KSTEPS 3125            // 100000 / 32
#define MPAD 256

#define SAF 8192               // A-stage floats (256*32)
#define SBF 2048               // B-stage floats (64*32)
#define STAGEF (SAF + 2*SBF)   // 12288 floats = 48KB per stage
#define GSMEM (2 * STAGEF * 4) // 96KB dynamic
#define HSMEM (MM * DD * 4)    // 102.4KB dynamic for k_hops

// ---------------- scratch (allocation-free) ----------------
__device__ float g_qd[DD];
__device__ float g_A2[MPAD * DD];   // tA + memory @ Wa^T (split-K atomic accum)
__device__ float g_C2[MPAD * DD];   // tC + memory @ Wc^T

__device__ __forceinline__ float warp_sum(float v) {
#pragma unroll
    for (int o = 16; o > 0; o >>= 1) v += __shfl_xor_sync(0xffffffffu, v, o);
    return v;
}

__device__ __forceinline__ float warp_max(float v) {
#pragma unroll
    for (int o = 16; o > 0; o >>= 1) v = fmaxf(v, __shfl_xor_sync(0xffffffffu, v, o));
    return v;
}

__device__ __forceinline__ unsigned f2tf32(float x) {
    unsigned r;
    asm("cvt.rna.tf32.f32 %0, %1;" : "=r"(r) : "f"(x));
    return r;
}

__device__ __forceinline__ void mma8(float* c, const unsigned* a, unsigned b0, unsigned b1) {
    asm volatile(
        "mma.sync.aligned.m16n8k8.row.col.f32.tf32.tf32.f32 "
        "{%0,%1,%2,%3},{%4,%5,%6,%7},{%8,%9},{%0,%1,%2,%3};"
        : "+f"(c[0]), "+f"(c[1]), "+f"(c[2]), "+f"(c[3])
        : "r"(a[0]), "r"(a[1]), "r"(a[2]), "r"(a[3]), "r"(b0), "r"(b1));
}

__device__ __forceinline__ void cpa16(unsigned saddr, const void* g) {
    asm volatile("cp.async.ca.shared.global [%0], [%1], 16;\n"
                 :: "r"(saddr), "l"(g));
}

// swizzled smem index for element (r, k) in a 32-wide tile (16B-granular XOR)
__device__ __forceinline__ int swz(int r, int k) {
    return r * 32 + (k ^ ((r & 7) << 2));
}

// fold temporal matrices into the accumulators (reset every replay)
__global__ void k_init(const float* __restrict__ tA, const float* __restrict__ tC) {
    int i = blockIdx.x * blockDim.x + threadIdx.x;
    if (i < MPAD * DD) {
        g_A2[i] = (i < MM * DD) ? tA[i] : 0.f;
        g_C2[i] = (i < MM * DD) ? tC[i] : 0.f;
    }
    if (i < DD) g_qd[i] = 0.f;
}

// ---------------- qd0 = question @ Wb^T (fp32 exact) ----------------
__global__ void __launch_bounds__(256) k_quesd(
    const float* __restrict__ Wb, const float* __restrict__ question) {
    __shared__ float sred[8];
    const int tid = threadIdx.x, lane = tid & 31, w = tid >> 5;
    const int r = blockIdx.x >> 1, half = blockIdx.x & 1;
    const float4* wr = (const float4*)(Wb + (size_t)r * VV + half * 50000);
    const float4* qv = (const float4*)(question + half * 50000);
    float acc = 0.f;
    for (int q = tid; q < 12500; q += 256) {
        float4 a = wr[q], b = qv[q];
        acc += a.x * b.x + a.y * b.y + a.z * b.z + a.w * b.w;
    }
    acc = warp_sum(acc);
    if (lane == 0) sred[w] = acc;
    __syncthreads();
    if (w == 0) {
        float x = (lane < 8) ? sred[lane] : 0.f;
        x = warp_sum(x);
        if (lane == 0) atomicAdd(&g_qd[r], x);
    }
}

// ---------------- A2/C2 GEMM: 1xTF32, cp.async double-buffered ----------------
// (byte-identical to the measured-best R9 kernel)
__global__ void __launch_bounds__(512, 1) k_gemm(
    const float* __restrict__ mem, const float* __restrict__ Wa,
    const float* __restrict__ Wc) {
    extern __shared__ float dsm[];

    const int tid = threadIdx.x, lane = tid & 31, w = tid >> 5;
    const int gid = lane >> 2, tig = lane & 3;
    const int nh = blockIdx.y;
    const int wm = w & 7, wn = w >> 3;
    const int mb = wm * 32, nb = wn * 32;
    const int s0 = (int)blockIdx.x * KSTEPS / NKS;
    const int s1 = ((int)blockIdx.x + 1) * KSTEPS / NKS;

    int amc[4];
#pragma unroll
    for (int i = 0; i < 4; i++) {
        int m = (tid + i * 512) >> 3;
        amc[i] = (m < MM) ? m : (MM - 1);   // clamp: rows>=200 garbage, never read
    }
    const int ac4 = (tid & 7) * 4;
    const int bn = tid >> 3;

    const unsigned sbase = (unsigned)__cvta_generic_to_shared(dsm);

    float accA[2][4][4], accC[2][4][4];
#pragma unroll
    for (int mt = 0; mt < 2; mt++)
#pragma unroll
        for (int nt = 0; nt < 4; nt++)
#pragma unroll
            for (int j = 0; j < 4; j++) { accA[mt][nt][j] = 0.f; accC[mt][nt][j] = 0.f; }

    auto issue = [&](int s, int p) {
        const int k0 = s * 32;
        const unsigned st = sbase + (unsigned)(p * STAGEF) * 4u;
#pragma unroll
        for (int i = 0; i < 4; i++)
            cpa16(st + (unsigned)swz(amc[i], ac4) * 4u,
                  mem + (size_t)amc[i] * VV + k0 + ac4);
        cpa16(st + (unsigned)(SAF + swz(bn, ac4)) * 4u,
              Wa + (size_t)(nh * 64 + bn) * VV + k0 + ac4);
        cpa16(st + (unsigned)(SAF + SBF + swz(bn, ac4)) * 4u,
              Wc + (size_t)(nh * 64 + bn) * VV + k0 + ac4);
        asm volatile("cp.async.commit_group;\n");
    };

    issue(s0, 0);
    for (int s = s0; s < s1; s++) {
        const int p = (s - s0) & 1;
        if (s + 1 < s1) {
            issue(s + 1, p ^ 1);                       // next stage in flight
            asm volatile("cp.async.wait_group 1;\n");  // current stage landed
        } else {
            asm volatile("cp.async.wait_group 0;\n");
        }
        __syncthreads();                               // all threads' copies visible

        const float* fA  = dsm + p * STAGEF;
        const float* fBa = fA + SAF;
        const float* fBc = fBa + SBF;
#pragma unroll
        for (int q = 0; q < 4; q++) {
            const int c0 = q * 8 + tig;
            unsigned a[2][4];
#pragma unroll
            for (int mt = 0; mt < 2; mt++) {
                const int r = mb + mt * 16 + gid;
                a[mt][0] = f2tf32(fA[swz(r, c0)]);
                a[mt][1] = f2tf32(fA[swz(r + 8, c0)]);
                a[mt][2] = f2tf32(fA[swz(r, c0 + 4)]);
                a[mt][3] = f2tf32(fA[swz(r + 8, c0 + 4)]);
            }
#pragma unroll
            for (int nt = 0; nt < 4; nt++) {
                const int n = nb + nt * 8 + gid;
                unsigned ba0 = f2tf32(fBa[swz(n, c0)]), ba1 = f2tf32(fBa[swz(n, c0 + 4)]);
                unsigned bc0 = f2tf32(fBc[swz(n, c0)]), bc1 = f2tf32(fBc[swz(n, c0 + 4)]);
#pragma unroll
                for (int mt = 0; mt < 2; mt++) {
                    mma8(accA[mt][nt], a[mt], ba0, ba1);
                    mma8(accC[mt][nt], a[mt], bc0, bc1);
                }
            }
        }
        __syncthreads();                               // reads done before refill
    }

    // split-K accumulate (on top of tA/tC baseline from k_init)
#pragma unroll
    for (int mt = 0; mt < 2; mt++)
#pragma unroll
        for (int nt = 0; nt < 4; nt++) {
            const int r0 = mb + mt * 16 + gid;
            const int c0 = nh * 64 + nb + nt * 8 + tig * 2;
            atomicAdd(&g_A2[r0 * DD + c0],           accA[mt][nt][0]);
            atomicAdd(&g_A2[r0 * DD + c0 + 1],       accA[mt][nt][1]);
            atomicAdd(&g_A2[(r0 + 8) * DD + c0],     accA[mt][nt][2]);
            atomicAdd(&g_A2[(r0 + 8) * DD + c0 + 1], accA[mt][nt][3]);
            atomicAdd(&g_C2[r0 * DD + c0],           accC[mt][nt][0]);
            atomicAdd(&g_C2[r0 * DD + c0 + 1],       accC[mt][nt][1]);
            atomicAdd(&g_C2[(r0 + 8) * DD + c0],     accC[mt][nt][2]);
            atomicAdd(&g_C2[(r0 + 8) * DD + c0 + 1], accC[mt][nt][3]);
        }
}

// ------- 3 hops, single block: At in regs, C2 in smem, shuffle softmax --------
// Barrier count: 4 __syncthreads per hop (was ~22).
__global__ void __launch_bounds__(512) k_hops() {
    extern __shared__ float sC[];             // [MM * DD] = 102.4 KB
    __shared__ float sqd[DD];
    __shared__ float sP[MM];
    __shared__ float sred[512];
    const int tid = threadIdx.x, lane = tid & 31, w = tid >> 5;
    const int mbase = w * 13;                 // warp-owned A rows (13 each)

    // C2 -> smem (one bulk copy), At -> registers
    {
        const float4* src = (const float4*)g_C2;
        float4* dst = (float4*)sC;
        for (int i = tid; i < MM * DD / 4; i += 512) dst[i] = src[i];
    }
    float ra[13][4];
#pragma unroll
    for (int i = 0; i < 13; i++) {
        const int m = mbase + i;
#pragma unroll
        for (int k = 0; k < 4; k++)
            ra[i][k] = (m < MM) ? g_A2[m * DD + lane + 32 * k] : 0.f;
    }
    if (tid < DD) sqd[tid] = g_qd[tid];
    __syncthreads();

    for (int h = 0; h < HOPS; h++) {
        // logits from registers -> sP
        float q0 = sqd[lane], q1 = sqd[lane + 32], q2 = sqd[lane + 64], q3 = sqd[lane + 96];
#pragma unroll
        for (int i = 0; i < 13; i++) {
            const int m = mbase + i;
            float acc = ra[i][0] * q0 + ra[i][1] * q1 + ra[i][2] * q2 + ra[i][3] * q3;
            acc = warp_sum(acc);
            if (lane == 0 && m < MM) sP[m] = acc;
        }
        __syncthreads();                                   // (1) logits complete

        // softmax entirely within warp 0 (shuffle reductions, no block barriers)
        if (w == 0) {
            float lv[7];
            float mx = -3.4e38f;
#pragma unroll
            for (int i = 0; i < 7; i++) {
                const int m = lane + 32 * i;
                lv[i] = (m < MM) ? sP[m] : -3.4e38f;
                mx = fmaxf(mx, lv[i]);
            }
            mx = warp_max(mx);
            float sum = 0.f;
#pragma unroll
            for (int i = 0; i < 7; i++) {
                lv[i] = (lane + 32 * i < MM) ? __expf(lv[i] - mx) : 0.f;
                sum += lv[i];
            }
            sum = warp_sum(sum);
            const float inv = 1.f / sum;
#pragma unroll
            for (int i = 0; i < 7; i++) {
                const int m = lane + 32 * i;
                if (m < MM) sP[m] = lv[i] * inv;
            }
        }
        __syncthreads();                                   // (2) P ready

        // o[d] = qd[d] + sum_m P[m]*C2[m][d]  (4-way m-split, all smem)
        {
            const int q = tid >> 7, d = tid & 127;
            float part = 0.f;
#pragma unroll 10
            for (int m = q * 50; m < q * 50 + 50; m++)
                part += sP[m] * sC[m * DD + d];
            sred[tid] = part;
            __syncthreads();                               // (3) partials ready
            float o = 0.f;
            if (q == 0)
                o = sqd[d] + sred[d] + sred[d + 128] + sred[d + 256] + sred[d + 384];
            __syncthreads();
            if (q == 0) sqd[d] = o;
            __syncthreads();                               // (4) qd updated
        }
    }
    if (tid < DD) g_qd[tid] = sqd[tid];
}

// ---------------- out[v] = o . Wout[v] ----------------
__global__ void __launch_bounds__(256) k_out(
    const float* __restrict__ Wout, float* __restrict__ out) {
    const int lane = threadIdx.x & 31;
    const int gw = (blockIdx.x * 256 + threadIdx.x) >> 5;
    const int nw = (gridDim.x * 256) >> 5;
    float4 qv = *(const float4*)(&g_qd[lane * 4]);
    for (int r = gw; r < VV; r += nw) {
        float4 wv = ((const float4*)(Wout + (size_t)r * DD))[lane];
        float acc = qv.x * wv.x + qv.y * wv.y + qv.z * wv.z + qv.w * wv.w;
        acc = warp_sum(acc);
        if (lane == 0) out[r] = acc;
    }
}

extern "C" void kernel_launch(void* const* d_in, const int* in_sizes, int n_in,
                              void* d_out, int out_size) {
    const float* question = (const float*)d_in[0];
    const float* memory   = (const float*)d_in[1];
    const float* Wa       = (const float*)d_in[2];
    const float* Wb       = (const float*)d_in[3];
    const float* Wc       = (const float*)d_in[4];
    const float* Wout     = (const float*)d_in[5];
    const float* tA       = (const float*)d_in[6];
    const float* tC       = (const float*)d_in[7];
    float* out = (float*)d_out;

    // idempotent dynamic-smem opt-ins (no static guards)
    cudaFuncSetAttribute(k_gemm, cudaFuncAttributeMaxDynamicSharedMemorySize, GSMEM);
    cudaFuncSetAttribute(k_hops, cudaFuncAttributeMaxDynamicSharedMemorySize, HSMEM);

    k_init<<<32, 1024>>>(tA, tC);
    k_gemm<<<dim3(NKS, 2), 512, GSMEM>>>(memory, Wa, Wc);
    k_quesd<<<DD * 2, 256>>>(Wb, question);
    k_hops<<<1, 512, HSMEM>>>();
    k_out<<<592, 256>>>(Wout, out);
}